// round 14
// baseline (speedup 1.0000x reference)
#include <cuda_runtime.h>
#include <cuda_fp16.h>
#include <math.h>

#define BB   128
#define SS   400
#define EE   512
#define TT   300
#define VV   30
#define EMBD 256
#define H1   512
#define H2   128
#define PP   128
#define G1   2048
#define G2   512
#define NCTA 128
#define NTHR 256
#define PRED_N (BB*VV*TT)

typedef unsigned long long u64;

// ---------------- device scratch (no cudaMalloc allowed) ----------------
__device__ __align__(16) __half  g_keysh [BB*SS*PP];   // fp16 keys [b][s][p]
__device__ __align__(16) __half  g_valsh [BB*SS*PP];   // fp16 values [b][s][p]
__device__ __align__(16) __half  g_W1h   [640*G1];     // [k][j]: k<128 ctx cols of W_ih1, else W_hh1
__device__ __align__(16) __half  g_W2h   [640*G2];     // [k][j]: k<512 W_ih2, else W_hh2
__device__ __align__(16) float   g_MembT [G1*32];      // [j][tok]: emb contribution + b_ih1 + b_hh1
__device__ __align__(16) float   g_b2    [G2];         // b_ih2 + b_hh2
__device__ __align__(16) float   g_part1 [4][G1*BB];   // LSTM1 gate partials, [ks][j][b]
__device__ __align__(16) float   g_part2 [16][G2*BB];  // LSTM2 gate partials, [ks][j][b]
__device__ __align__(16) float   g_xT    [768*BB];     // [k][b]: 0-127 ctx, 128-639 h1, 640-767 h2prev
__device__ __align__(16) float   g_c1T   [H1*BB];      // [h][b] (same-CTA read/write)
__device__ __align__(16) float   g_c2    [BB*H2];      // [b][h] (same-CTA read/write)
__device__ unsigned g_flags[NCTA*32];

__device__ __forceinline__ float sigf(float x) { return 1.f / (1.f + expf(-x)); }

__device__ __forceinline__ u64 ffma2(u64 a, u64 b, u64 c) {
    u64 d; asm("fma.rn.f32x2 %0,%1,%2,%3;" : "=l"(d) : "l"(a), "l"(b), "l"(c)); return d;
}
__device__ __forceinline__ u64 pack2(float v) {
    u64 d; asm("mov.b64 %0,{%1,%1};" : "=l"(d) : "f"(v)); return d;
}
__device__ __forceinline__ unsigned ld_acq(unsigned* p) {
    unsigned v; asm volatile("ld.acquire.gpu.u32 %0, [%1];" : "=r"(v) : "l"(p) : "memory"); return v;
}
__device__ __forceinline__ void st_rel(unsigned* p, unsigned v) {
    asm volatile("st.release.gpu.u32 [%0], %1;" :: "l"(p), "r"(v) : "memory");
}

__device__ __forceinline__ void fma16(float4& a0, float4& a1, float4& a2, float4& a3,
                                      float4 xv, float4 wv) {
    a0.x += xv.x*wv.x; a0.y += xv.x*wv.y; a0.z += xv.x*wv.z; a0.w += xv.x*wv.w;
    a1.x += xv.y*wv.x; a1.y += xv.y*wv.y; a1.z += xv.y*wv.z; a1.w += xv.y*wv.w;
    a2.x += xv.z*wv.x; a2.y += xv.z*wv.y; a2.z += xv.z*wv.z; a2.w += xv.z*wv.w;
    a3.x += xv.w*wv.x; a3.y += xv.w*wv.y; a3.z += xv.w*wv.z; a3.w += xv.w*wv.w;
}

// ---- fence-free grid barrier: release-store arrival, acquire-load poll, backoff ----
// No CCTL.IVALL is ever emitted -> L1 stays warm with read-only weights.
// All cross-CTA mutable data is accessed with __ldcg (L2) for coherence.
__device__ __forceinline__ void gridbar(int cta, int tid, unsigned& epoch) {
    epoch++;
    __syncthreads();
    if (tid == 0) st_rel(&g_flags[cta * 32], epoch);
    if (tid < NCTA) {
        if (ld_acq(&g_flags[tid * 32]) < epoch) {
            while (ld_acq(&g_flags[tid * 32]) < epoch) __nanosleep(32);
        }
    }
    __syncthreads();
}

// ---------------- precompute kernels ----------------
__global__ void pack_kernel(const float* __restrict__ Wih1, const float* __restrict__ Whh1,
                            const float* __restrict__ Wih2, const float* __restrict__ Whh2,
                            const float* __restrict__ bih2, const float* __restrict__ bhh2) {
    int gid = blockIdx.x * blockDim.x + threadIdx.x;
    if (gid < 640 * G1) {
        int k = gid / G1, j = gid % G1;
        float w = (k < PP) ? Wih1[j * (EMBD + PP) + k] : Whh1[j * H1 + (k - PP)];
        g_W1h[gid] = __float2half(w);
    } else if (gid < 640 * G1 + 640 * G2) {
        int g2 = gid - 640 * G1;
        int k = g2 / G2, j = g2 % G2;
        float w = (k < H1) ? Wih2[j * H1 + k] : Whh2[j * H2 + (k - H1)];
        g_W2h[g2] = __float2half(w);
    } else {
        int g3 = gid - 640 * G1 - 640 * G2;
        if (g3 < G2) g_b2[g3] = bih2[g3] + bhh2[g3];
    }
}

__global__ void memb_kernel(const float* __restrict__ emb, const float* __restrict__ Wih1,
                            const float* __restrict__ bih1, const float* __restrict__ bhh1) {
    int gid = blockIdx.x * blockDim.x + threadIdx.x;
    if (gid >= VV * G1) return;
    int v = gid / G1, j = gid % G1;
    const float* er = emb + v * EMBD;
    const float* wr = Wih1 + j * (EMBD + PP) + PP;   // emb part of x
    float s = bih1[j] + bhh1[j];
    for (int k = 0; k < EMBD; k++) s += er[k] * wr[k];
    g_MembT[j * 32 + v] = s;
}

// keys/values: out[row][p] = enc[row] . W[p] + bias[p] (fp32 compute, fp16 store)
__global__ __launch_bounds__(256) void kv_kernel(
    const float* __restrict__ enc,
    const float* __restrict__ Wk, const float* __restrict__ bk,
    const float* __restrict__ Wv, const float* __restrict__ bv) {
    __shared__ float sh[10752];
    float* xs = sh;          // [64][132]
    float* ws = sh + 8448;   // [64][36]
    int rt = blockIdx.x;
    int m = blockIdx.y;
    int mat = m >> 2, jt = m & 3;
    const float* W    = mat ? Wv : Wk;
    const float* bias = mat ? bv : bk;
    __half* outh      = mat ? g_valsh : g_keysh;
    int r0 = rt * 128, j0 = jt * 32;
    int tid = threadIdx.x;
    int tb = tid >> 3, tj = tid & 7;
    float4 a0 = {0,0,0,0}, a1 = a0, a2 = a0, a3 = a0;
    for (int kc = 0; kc < EE; kc += 64) {
        #pragma unroll
        for (int i = 0; i < 32; i++) {
            int lin = i * 256 + tid;
            int br = lin >> 6, kk = lin & 63;
            xs[kk * 132 + br] = enc[(size_t)(r0 + br) * EE + kc + kk];
        }
        #pragma unroll
        for (int i = 0; i < 8; i++) {
            int lin = i * 256 + tid;
            int jj = lin >> 6, kk = lin & 63;
            ws[kk * 36 + jj] = W[(j0 + jj) * EE + kc + kk];
        }
        __syncthreads();
        #pragma unroll 16
        for (int kk = 0; kk < 64; kk++) {
            float4 xv = *(const float4*)&xs[kk * 132 + tb * 4];
            float4 wv = *(const float4*)&ws[kk * 36 + tj * 4];
            fma16(a0, a1, a2, a3, xv, wv);
        }
        __syncthreads();
    }
    float4 bb = *(const float4*)&bias[j0 + tj * 4];
    a0.x += bb.x; a0.y += bb.y; a0.z += bb.z; a0.w += bb.w;
    a1.x += bb.x; a1.y += bb.y; a1.z += bb.z; a1.w += bb.w;
    a2.x += bb.x; a2.y += bb.y; a2.z += bb.z; a2.w += bb.w;
    a3.x += bb.x; a3.y += bb.y; a3.z += bb.z; a3.w += bb.w;
    int co = j0 + tj * 4;
    #pragma unroll
    for (int r = 0; r < 4; r++) {
        float4 a = (r == 0) ? a0 : (r == 1) ? a1 : (r == 2) ? a2 : a3;
        __half* dst = outh + (size_t)(r0 + tb * 4 + r) * PP + co;
        *(__half2*)(dst)     = __floats2half2_rn(a.x, a.y);
        *(__half2*)(dst + 2) = __floats2half2_rn(a.z, a.w);
    }
}

// zero states, context0 = mean_s(values) into xT rows 0-127
__global__ void init_kernel() {
    int gid = blockIdx.x * blockDim.x + threadIdx.x;
    if (gid < 640 * BB) g_xT[128 * BB + gid] = 0.f;    // h1 + h2prev rows
    if (gid < H1 * BB)  g_c1T[gid] = 0.f;
    if (gid < BB * H2)  g_c2[gid] = 0.f;
    if (gid < BB * PP) {
        int b = gid >> 7, p = gid & 127;
        float s = 0.f;
        for (int ss = 0; ss < SS; ss++) s += __half2float(g_valsh[((size_t)b * SS + ss) * PP + p]);
        g_xT[p * BB + b] = s * (1.f / SS);
    }
    if (gid < NCTA) g_flags[gid * 32] = 0u;            // reset barrier epochs every run
}

// ---------------- the persistent decode loop ----------------
__global__ __launch_bounds__(NTHR, 1) void loop_kernel(
    const int* __restrict__ y, const int* __restrict__ lens,
    const float* __restrict__ Wq, const float* __restrict__ bq,
    const float* __restrict__ emb, const float* __restrict__ bout,
    float* __restrict__ out) {
    __align__(16) __shared__ float sh[4608];
    const int cta = blockIdx.x;
    const int tid = threadIdx.x;
    unsigned epoch = 0u;   // init_kernel reset flags to 0 this launch

    for (int t = 0; t < TT; t++) {
        // ---- Stage A: LSTM1 gates out1[j][b] = sum_k xT[k][b]*W1[k][j], K=640, 4-way k-split ----
        {
            float* xs = sh;            // [16][128] = 2048
            float* ws = sh + 2048;     // [16][64]  = 1024
            const int rg = tid & 15, jg = tid >> 4;
            const int r0 = rg * 8, cA = jg * 4;
            const int jt = cta >> 2, ks = cta & 3;
            const int j0 = jt * 64, kb = ks * 160;
            u64 acc[4][4];
            #pragma unroll
            for (int i = 0; i < 4; i++)
                #pragma unroll
                for (int c = 0; c < 4; c++) acc[i][c] = 0ull;
            for (int kc = 0; kc < 160; kc += 16) {
                #pragma unroll
                for (int i = 0; i < 8; i++) {
                    int lin = i * 256 + tid;
                    int kk = lin >> 7, x = lin & 127;
                    xs[kk * 128 + x] = __ldcg(&g_xT[(kb + kc + kk) * BB + x]);
                }
                #pragma unroll
                for (int i = 0; i < 2; i++) {
                    int lin = i * 256 + tid;
                    int kk = lin >> 5, x2 = lin & 31;
                    __half2 hv = *(const __half2*)(g_W1h + (size_t)(kb + kc + kk) * G1 + j0 + 2 * x2);
                    float2 f = __half22float2(hv);
                    *(float2*)&ws[kk * 64 + 2 * x2] = f;
                }
                __syncthreads();
                #pragma unroll
                for (int kk = 0; kk < 16; kk++) {
                    ulonglong2 xa = *(const ulonglong2*)&xs[kk * 128 + r0];
                    ulonglong2 xb = *(const ulonglong2*)&xs[kk * 128 + r0 + 4];
                    float4 wA = *(const float4*)&ws[kk * 64 + cA];
                    u64 w[4] = {pack2(wA.x), pack2(wA.y), pack2(wA.z), pack2(wA.w)};
                    u64 xr[4] = {xa.x, xa.y, xb.x, xb.y};
                    #pragma unroll
                    for (int i = 0; i < 4; i++)
                        #pragma unroll
                        for (int c = 0; c < 4; c++) acc[i][c] = ffma2(xr[i], w[c], acc[i][c]);
                }
                __syncthreads();
            }
            float* dst = g_part1[ks];
            #pragma unroll
            for (int c = 0; c < 4; c++) {
                *(ulonglong2*)&dst[(size_t)(j0 + cA + c) * BB + r0]     = make_ulonglong2(acc[0][c], acc[1][c]);
                *(ulonglong2*)&dst[(size_t)(j0 + cA + c) * BB + r0 + 4] = make_ulonglong2(acc[2][c], acc[3][c]);
            }
        }
        gridbar(cta, tid, epoch);

        // ---- Stage B: LSTM1 cell update, h1 -> xT rows 128-639 ----
        {
            int* stok = (int*)(sh + 4352);
            if (tid < BB) stok[tid] = (t == 0) ? 0 : y[tid * TT + t];
            __syncthreads();
            #pragma unroll
            for (int e = 0; e < 2; e++) {
                int idx = cta * 512 + e * 256 + tid;
                int h = idx >> 7, b = idx & 127;
                int tok = stok[b];
                float gi = g_MembT[(size_t)h * 32 + tok];
                float gf = g_MembT[(size_t)(512 + h) * 32 + tok];
                float gg = g_MembT[(size_t)(1024 + h) * 32 + tok];
                float go = g_MembT[(size_t)(1536 + h) * 32 + tok];
                #pragma unroll
                for (int ks = 0; ks < 4; ks++) {
                    const float* p = g_part1[ks];
                    gi += __ldcg(&p[(size_t)h * BB + b]);
                    gf += __ldcg(&p[(size_t)(512 + h) * BB + b]);
                    gg += __ldcg(&p[(size_t)(1024 + h) * BB + b]);
                    go += __ldcg(&p[(size_t)(1536 + h) * BB + b]);
                }
                float c = sigf(gf) * g_c1T[h * BB + b] + sigf(gi) * tanhf(gg);
                g_c1T[h * BB + b] = c;
                g_xT[(128 + h) * BB + b] = sigf(go) * tanhf(c);
            }
        }
        gridbar(cta, tid, epoch);

        // ---- Stage B2: LSTM2 gates over x2=[h1;h2prev] (xT rows 128-767), K=640, 16-way split ----
        {
            float* xs = sh;            // [20][128] = 2560
            float* ws = sh + 2560;     // [20][64]  = 1280
            const int rg = tid & 15, jg = tid >> 4;
            const int r0 = rg * 8, cA = jg * 4;
            const int jt = cta >> 4, ks = cta & 15;
            const int j0 = jt * 64, kb = 128 + ks * 40;
            u64 acc[4][4];
            #pragma unroll
            for (int i = 0; i < 4; i++)
                #pragma unroll
                for (int c = 0; c < 4; c++) acc[i][c] = 0ull;
            for (int kc = 0; kc < 40; kc += 20) {
                #pragma unroll
                for (int i = 0; i < 10; i++) {
                    int lin = i * 256 + tid;
                    int kk = lin >> 7, b = lin & 127;
                    xs[kk * 128 + b] = __ldcg(&g_xT[(kb + kc + kk) * BB + b]);
                }
                #pragma unroll
                for (int i = 0; i < 3; i++) {
                    int lin = i * 256 + tid;
                    if (lin < 640) {
                        int kk = lin >> 5, x2 = lin & 31;
                        __half2 hv = *(const __half2*)(g_W2h + (size_t)(kb - 128 + kc + kk) * G2 + j0 + 2 * x2);
                        float2 f = __half22float2(hv);
                        *(float2*)&ws[kk * 64 + 2 * x2] = f;
                    }
                }
                __syncthreads();
                #pragma unroll
                for (int kk = 0; kk < 20; kk++) {
                    ulonglong2 xa = *(const ulonglong2*)&xs[kk * 128 + r0];
                    ulonglong2 xb = *(const ulonglong2*)&xs[kk * 128 + r0 + 4];
                    float4 wA = *(const float4*)&ws[kk * 64 + cA];
                    u64 w[4] = {pack2(wA.x), pack2(wA.y), pack2(wA.z), pack2(wA.w)};
                    u64 xr[4] = {xa.x, xa.y, xb.x, xb.y};
                    #pragma unroll
                    for (int i = 0; i < 4; i++)
                        #pragma unroll
                        for (int c = 0; c < 4; c++) acc[i][c] = ffma2(xr[i], w[c], acc[i][c]);
                }
                __syncthreads();
            }
            float* dst = g_part2[ks];
            #pragma unroll
            for (int c = 0; c < 4; c++) {
                *(ulonglong2*)&dst[(size_t)(j0 + cA + c) * BB + r0]     = make_ulonglong2(acc[0][c], acc[1][c]);
                *(ulonglong2*)&dst[(size_t)(j0 + cA + c) * BB + r0 + 4] = make_ulonglong2(acc[2][c], acc[3][c]);
            }
        }
        gridbar(cta, tid, epoch);

        // ---- Stage C: per-batch CTA: LSTM2 cell, q, attention, context, logits ----
        {
            const int b = cta;
            float* sg   = sh;            // 512
            float* h2s  = sh + 512;      // 128
            float* qs   = sh + 640;      // 128 (reused as ctx)
            float* satt = sh + 768;      // 400
            float* red  = sh + 1200;     // 8
            float* sinv = sh + 1216;     // 1
            float* cred = sh + 1456;     // 256

            #pragma unroll
            for (int e = 0; e < 2; e++) {
                int j = e * 256 + tid;
                float s = g_b2[j];
                #pragma unroll
                for (int ks = 0; ks < 16; ks++) s += __ldcg(&g_part2[ks][(size_t)j * BB + b]);
                sg[j] = s;
            }
            __syncthreads();
            if (tid < H2) {
                int h = tid;
                float c = sigf(sg[128 + h]) * g_c2[b * H2 + h] + sigf(sg[h]) * tanhf(sg[256 + h]);
                g_c2[b * H2 + h] = c;
                float hh = sigf(sg[384 + h]) * tanhf(c);
                g_xT[(640 + h) * BB + b] = hh;   // h2prev for next step
                h2s[h] = hh;
            }
            __syncthreads();
            if (tid < PP) {
                const float* wr = Wq + tid * H2;
                float s = bq[tid];
                for (int k = 0; k < H2; k++) s += h2s[k] * wr[k];
                qs[tid] = s;
            }
            __syncthreads();
            int lenb = lens[b];
            const float scale = 0.08838834764831845f;   // 1/sqrt(128)
            float pmax = -3.4e38f;
            for (int s = tid; s < SS; s += NTHR) {
                const __half2* kr = (const __half2*)(g_keysh + ((size_t)b * SS + s) * PP);
                float d = 0.f;
                #pragma unroll 8
                for (int p2 = 0; p2 < 64; p2++) {
                    float2 kf = __half22float2(__ldcg(kr + p2));
                    d += kf.x * qs[2 * p2] + kf.y * qs[2 * p2 + 1];
                }
                d *= scale;
                if (s >= lenb) d = -1e9f;
                satt[s] = d;
                pmax = fmaxf(pmax, d);
            }
            // warp-shuffle max reduction
            float m = pmax;
            #pragma unroll
            for (int o = 16; o > 0; o >>= 1) m = fmaxf(m, __shfl_xor_sync(0xffffffffu, m, o));
            if ((tid & 31) == 0) red[tid >> 5] = m;
            __syncthreads();
            float mx = red[0];
            #pragma unroll
            for (int i = 1; i < 8; i++) mx = fmaxf(mx, red[i]);
            __syncthreads();
            float psum = 0.f;
            for (int s = tid; s < SS; s += NTHR) {
                float e = expf(satt[s] - mx);
                satt[s] = e;
                psum += e;
            }
            #pragma unroll
            for (int o = 16; o > 0; o >>= 1) psum += __shfl_xor_sync(0xffffffffu, psum, o);
            if ((tid & 31) == 0) red[tid >> 5] = psum;
            __syncthreads();
            if (tid == 0) {
                float s = 0.f;
                #pragma unroll
                for (int i = 0; i < 8; i++) s += red[i];
                sinv[0] = 1.f / s;
            }
            __syncthreads();
            float inv = sinv[0];
            {
                int p = tid & 127, half_ = tid >> 7;
                float c = 0.f;
                int s0 = half_ * 200;
                const __half* vp = g_valsh + ((size_t)b * SS + s0) * PP + p;
                for (int s = 0; s < 200; s++)
                    c += satt[s0 + s] * __half2float(__ldcg(vp + (size_t)s * PP));
                cred[tid] = c;
            }
            __syncthreads();
            if (tid < PP) {
                float c = (cred[tid] + cred[tid + 128]) * inv;
                g_xT[tid * BB + b] = c;   // ctx for next step
                qs[tid] = c;
            }
            __syncthreads();
            // logits: 240 threads (30 v x 8 chunks of 32), warp-shuffle reduce per v
            {
                int v = tid >> 3, ch = tid & 7;
                float lg = 0.f;
                if (v < VV) {
                    const float* er = emb + v * EMBD + ch * 32;
                    if (ch < 4) {
                        const float* src = qs + ch * 32;
                        #pragma unroll 8
                        for (int e = 0; e < 32; e++) lg += src[e] * er[e];
                    } else {
                        const float* src = h2s + (ch - 4) * 32;
                        #pragma unroll 8
                        for (int e = 0; e < 32; e++) lg += src[e] * er[e];
                    }
                }
                lg += __shfl_down_sync(0xffffffffu, lg, 4, 8);
                lg += __shfl_down_sync(0xffffffffu, lg, 2, 8);
                lg += __shfl_down_sync(0xffffffffu, lg, 1, 8);
                if (v < VV && ch == 0)
                    out[((size_t)b * VV + v) * TT + t] = lg + bout[v];   // predictions [B,V,T]
            }
            if (b == 0) {
                for (int s = tid; s < SS; s += NTHR)
                    out[PRED_N + t * SS + s] = satt[s] * inv;  // attention_plot [T,S]
            }
        }
        gridbar(cta, tid, epoch);
    }
}

// ---------------- launch ----------------
extern "C" void kernel_launch(void* const* d_in, const int* in_sizes, int n_in,
                              void* d_out, int out_size) {
    (void)in_sizes; (void)n_in; (void)out_size;
    const float* enc  = (const float*)d_in[0];
    const int*   lens = (const int*)d_in[1];
    const int*   y    = (const int*)d_in[2];
    const float* emb  = (const float*)d_in[3];
    const float* Wih1 = (const float*)d_in[4];
    const float* Whh1 = (const float*)d_in[5];
    const float* bih1 = (const float*)d_in[6];
    const float* bhh1 = (const float*)d_in[7];
    const float* Wih2 = (const float*)d_in[8];
    const float* Whh2 = (const float*)d_in[9];
    const float* bih2 = (const float*)d_in[10];
    const float* bhh2 = (const float*)d_in[11];
    const float* Wk   = (const float*)d_in[12];
    const float* bk   = (const float*)d_in[13];
    const float* Wv   = (const float*)d_in[14];
    const float* bv   = (const float*)d_in[15];
    const float* Wq   = (const float*)d_in[16];
    const float* bq   = (const float*)d_in[17];
    const float* bout = (const float*)d_in[18];
    float* out = (float*)d_out;

    int pack_n = 640 * G1 + 640 * G2 + G2;
    pack_kernel<<<(pack_n + 255) / 256, 256>>>(Wih1, Whh1, Wih2, Whh2, bih2, bhh2);
    memb_kernel<<<(VV * G1 + 255) / 256, 256>>>(emb, Wih1, bih1, bhh1);
    kv_kernel<<<dim3(400, 8), 256>>>(enc, Wk, bk, Wv, bv);
    init_kernel<<<320, 256>>>();
    loop_kernel<<<NCTA, NTHR>>>(y, lens, Wq, bq, emb, bout, out);
}

// round 15
// speedup vs baseline: 1.1233x; 1.1233x over previous
#include <cuda_runtime.h>
#include <cuda_fp16.h>
#include <math.h>

#define BB   128
#define SS   400
#define EE   512
#define TT   300
#define VV   30
#define EMBD 256
#define H1   512
#define H2   128
#define PP   128
#define G1   2048
#define G2   512
#define NCTA 128
#define NTHR 256
#define PRED_N (BB*VV*TT)

typedef unsigned long long u64;

// ---------------- device scratch (no cudaMalloc allowed) ----------------
// Gate-interleaved column order everywhere: jnew = 4*h + gate (gate: 0=i,1=f,2=g,3=o)
__device__ __align__(16) __half  g_keysh [BB*SS*PP];   // fp16 keys [b][s][p]
__device__ __align__(16) __half  g_valsh [BB*SS*PP];   // fp16 values [b][s][p]
__device__ __align__(16) __half  g_W1h   [640*G1];     // [k][jnew]: k<128 ctx cols, else W_hh1
__device__ __align__(16) __half  g_W2h   [640*G2];     // [k][jnew]: k<512 W_ih2, else W_hh2
__device__ __align__(16) float   g_MembT [G1*32];      // [jnew][tok]
__device__ __align__(16) float   g_b2    [G2];         // [jnew] b_ih2+b_hh2
__device__ __align__(16) float   g_part1 [2][G1*BB];   // LSTM1 partials, [kh][jnew][b]
__device__ __align__(16) float   g_part2 [4][G2*BB];   // LSTM2 partials, [ks][jnew][b]
// xT rows: [0,128) ctx | [128,640) h1 slot0 | [640,1152) h1 slot1 | [1152,1280) h2prev
__device__ __align__(16) float   g_xT    [1280*BB];
__device__ __align__(16) float   g_c1T   [H1*BB];      // [h][b], single-CTA owner
__device__ __align__(16) float   g_c2    [BB*H2];      // [b][h], single-CTA owner
__device__ unsigned g_flags [NCTA*32];                 // global barrier epochs
__device__ unsigned g_pflags[NCTA*32];                 // AB pairwise flags

__device__ __forceinline__ float sigf(float x) { return 1.f / (1.f + expf(-x)); }

__device__ __forceinline__ u64 ffma2(u64 a, u64 b, u64 c) {
    u64 d; asm("fma.rn.f32x2 %0,%1,%2,%3;" : "=l"(d) : "l"(a), "l"(b), "l"(c)); return d;
}
__device__ __forceinline__ u64 pack2(float v) {
    u64 d; asm("mov.b64 %0,{%1,%1};" : "=l"(d) : "f"(v)); return d;
}
__device__ __forceinline__ unsigned ld_acq(unsigned* p) {
    unsigned v; asm volatile("ld.acquire.gpu.u32 %0, [%1];" : "=r"(v) : "l"(p) : "memory"); return v;
}
__device__ __forceinline__ void st_rel(unsigned* p, unsigned v) {
    asm volatile("st.release.gpu.u32 [%0], %1;" :: "l"(p), "r"(v) : "memory");
}

__device__ __forceinline__ void fma16(float4& a0, float4& a1, float4& a2, float4& a3,
                                      float4 xv, float4 wv) {
    a0.x += xv.x*wv.x; a0.y += xv.x*wv.y; a0.z += xv.x*wv.z; a0.w += xv.x*wv.w;
    a1.x += xv.y*wv.x; a1.y += xv.y*wv.y; a1.z += xv.y*wv.z; a1.w += xv.y*wv.w;
    a2.x += xv.z*wv.x; a2.y += xv.z*wv.y; a2.z += xv.z*wv.z; a2.w += xv.z*wv.w;
    a3.x += xv.w*wv.x; a3.y += xv.w*wv.y; a3.z += xv.w*wv.z; a3.w += xv.w*wv.w;
}

// ---- fence-free grid barrier: release arrival, hot acquire poll (no nanosleep) ----
__device__ __forceinline__ void gridbar(int cta, int tid, unsigned& epoch) {
    epoch++;
    __syncthreads();
    if (tid == 0) st_rel(&g_flags[cta * 32], epoch);
    if (tid < NCTA) { while (ld_acq(&g_flags[tid * 32]) < epoch) { } }
    __syncthreads();
}

// ---------------- precompute kernels ----------------
__global__ void pack_kernel(const float* __restrict__ Wih1, const float* __restrict__ Whh1,
                            const float* __restrict__ Wih2, const float* __restrict__ Whh2,
                            const float* __restrict__ bih2, const float* __restrict__ bhh2) {
    int gid = blockIdx.x * blockDim.x + threadIdx.x;
    if (gid < 640 * G1) {
        int k = gid / G1, jn = gid % G1;
        int h = jn >> 2, gate = jn & 3, jo = gate * H1 + h;
        float w = (k < PP) ? Wih1[jo * (EMBD + PP) + k] : Whh1[jo * H1 + (k - PP)];
        g_W1h[gid] = __float2half(w);
    } else if (gid < 640 * G1 + 640 * G2) {
        int g2 = gid - 640 * G1;
        int k = g2 / G2, jn = g2 % G2;
        int h = jn >> 2, gate = jn & 3, jo = gate * H2 + h;
        float w = (k < H1) ? Wih2[jo * H1 + k] : Whh2[jo * H2 + (k - H1)];
        g_W2h[g2] = __float2half(w);
    } else {
        int jn = gid - 640 * G1 - 640 * G2;
        if (jn < G2) {
            int h = jn >> 2, gate = jn & 3, jo = gate * H2 + h;
            g_b2[jn] = bih2[jo] + bhh2[jo];
        }
    }
}

__global__ void memb_kernel(const float* __restrict__ emb, const float* __restrict__ Wih1,
                            const float* __restrict__ bih1, const float* __restrict__ bhh1) {
    int gid = blockIdx.x * blockDim.x + threadIdx.x;
    if (gid >= VV * G1) return;
    int v = gid / G1, jn = gid % G1;
    int h = jn >> 2, gate = jn & 3, jo = gate * H1 + h;
    const float* er = emb + v * EMBD;
    const float* wr = Wih1 + jo * (EMBD + PP) + PP;
    float s = bih1[jo] + bhh1[jo];
    for (int k = 0; k < EMBD; k++) s += er[k] * wr[k];
    g_MembT[jn * 32 + v] = s;
}

// keys/values: out[row][p] = enc[row] . W[p] + bias[p] (fp32 compute, fp16 store)
__global__ __launch_bounds__(256) void kv_kernel(
    const float* __restrict__ enc,
    const float* __restrict__ Wk, const float* __restrict__ bk,
    const float* __restrict__ Wv, const float* __restrict__ bv) {
    __shared__ float sh[10752];
    float* xs = sh;          // [64][132]
    float* ws = sh + 8448;   // [64][36]
    int rt = blockIdx.x;
    int m = blockIdx.y;
    int mat = m >> 2, jt = m & 3;
    const float* W    = mat ? Wv : Wk;
    const float* bias = mat ? bv : bk;
    __half* outh      = mat ? g_valsh : g_keysh;
    int r0 = rt * 128, j0 = jt * 32;
    int tid = threadIdx.x;
    int tb = tid >> 3, tj = tid & 7;
    float4 a0 = {0,0,0,0}, a1 = a0, a2 = a0, a3 = a0;
    for (int kc = 0; kc < EE; kc += 64) {
        #pragma unroll
        for (int i = 0; i < 32; i++) {
            int lin = i * 256 + tid;
            int br = lin >> 6, kk = lin & 63;
            xs[kk * 132 + br] = enc[(size_t)(r0 + br) * EE + kc + kk];
        }
        #pragma unroll
        for (int i = 0; i < 8; i++) {
            int lin = i * 256 + tid;
            int jj = lin >> 6, kk = lin & 63;
            ws[kk * 36 + jj] = W[(j0 + jj) * EE + kc + kk];
        }
        __syncthreads();
        #pragma unroll 16
        for (int kk = 0; kk < 64; kk++) {
            float4 xv = *(const float4*)&xs[kk * 132 + tb * 4];
            float4 wv = *(const float4*)&ws[kk * 36 + tj * 4];
            fma16(a0, a1, a2, a3, xv, wv);
        }
        __syncthreads();
    }
    float4 bb = *(const float4*)&bias[j0 + tj * 4];
    a0.x += bb.x; a0.y += bb.y; a0.z += bb.z; a0.w += bb.w;
    a1.x += bb.x; a1.y += bb.y; a1.z += bb.z; a1.w += bb.w;
    a2.x += bb.x; a2.y += bb.y; a2.z += bb.z; a2.w += bb.w;
    a3.x += bb.x; a3.y += bb.y; a3.z += bb.z; a3.w += bb.w;
    int co = j0 + tj * 4;
    #pragma unroll
    for (int r = 0; r < 4; r++) {
        float4 a = (r == 0) ? a0 : (r == 1) ? a1 : (r == 2) ? a2 : a3;
        __half* dst = outh + (size_t)(r0 + tb * 4 + r) * PP + co;
        *(__half2*)(dst)     = __floats2half2_rn(a.x, a.y);
        *(__half2*)(dst + 2) = __floats2half2_rn(a.z, a.w);
    }
}

// zero states + both h1 slots + h2prev, context0 = mean_s(values), reset flags
__global__ void init_kernel() {
    int gid = blockIdx.x * blockDim.x + threadIdx.x;   // 640*256 = 163840 threads
    if (gid < 1152 * BB) g_xT[128 * BB + gid] = 0.f;   // h1 slots + h2prev
    if (gid < H1 * BB)  g_c1T[gid] = 0.f;
    if (gid < BB * H2)  g_c2[gid] = 0.f;
    if (gid < BB * PP) {
        int b = gid >> 7, p = gid & 127;
        float s = 0.f;
        for (int ss = 0; ss < SS; ss++) s += __half2float(g_valsh[((size_t)b * SS + ss) * PP + p]);
        g_xT[p * BB + b] = s * (1.f / SS);
    }
    if (gid < NCTA) { g_flags[gid * 32] = 0u; g_pflags[gid * 32] = 0u; }
}

// ---------------- the persistent decode loop ----------------
__global__ __launch_bounds__(NTHR, 1) void loop_kernel(
    const int* __restrict__ y, const int* __restrict__ lens,
    const float* __restrict__ Wq, const float* __restrict__ bq,
    const float* __restrict__ emb, const float* __restrict__ bout,
    float* __restrict__ out) {
    __align__(16) __shared__ float sh[10368];
    const int cta = blockIdx.x;
    const int tid = threadIdx.x;
    unsigned epoch = 0u;

    for (int t = 0; t < TT; t++) {
        const int RA = 128 + (t & 1) * 512;          // h1 read slot (rows)
        const int WA = 128 + ((t & 1) ^ 1) * 512;    // h1 write slot (rows)

        // ==== Stage AB: LSTM1 GEMM (2-way k-split, pairwise sync) + fused cell ====
        {
            float* xs = sh;          // [64][128]
            float* ws = sh + 8192;   // [64][32]
            const int jt = cta >> 1, kh = cta & 1;
            const int j0 = jt * 32, kb = kh * 320;
            const int tj = tid >> 4, tb = tid & 15;   // 2 j per tj, 8 b per tb
            u64 acc[2][4];
            #pragma unroll
            for (int i = 0; i < 2; i++)
                #pragma unroll
                for (int c = 0; c < 4; c++) acc[i][c] = 0ull;
            for (int kc = 0; kc < 320; kc += 64) {
                #pragma unroll
                for (int i = 0; i < 8; i++) {
                    int lin = i * 256 + tid;
                    int kk = lin >> 5, x4 = (lin & 31) * 4;
                    int k = kb + kc + kk;
                    int row = (k < 128) ? k : (RA - 128 + k);
                    *(float4*)&xs[kk * 128 + x4] = __ldcg((const float4*)&g_xT[row * BB + x4]);
                }
                #pragma unroll
                for (int i = 0; i < 4; i++) {
                    int lin = i * 256 + tid;
                    int kk = lin >> 4, x2 = (lin & 15) * 2;
                    __half2 hv = *(const __half2*)(g_W1h + (size_t)(kb + kc + kk) * G1 + j0 + x2);
                    *(float2*)&ws[kk * 32 + x2] = __half22float2(hv);
                }
                __syncthreads();
                #pragma unroll
                for (int kk = 0; kk < 64; kk++) {
                    float2 wv = *(const float2*)&ws[kk * 32 + tj * 2];
                    u64 w0 = pack2(wv.x), w1 = pack2(wv.y);
                    ulonglong2 xa = *(const ulonglong2*)&xs[kk * 128 + tb * 8];
                    ulonglong2 xb = *(const ulonglong2*)&xs[kk * 128 + tb * 8 + 4];
                    acc[0][0] = ffma2(xa.x, w0, acc[0][0]);
                    acc[0][1] = ffma2(xa.y, w0, acc[0][1]);
                    acc[0][2] = ffma2(xb.x, w0, acc[0][2]);
                    acc[0][3] = ffma2(xb.y, w0, acc[0][3]);
                    acc[1][0] = ffma2(xa.x, w1, acc[1][0]);
                    acc[1][1] = ffma2(xa.y, w1, acc[1][1]);
                    acc[1][2] = ffma2(xb.x, w1, acc[1][2]);
                    acc[1][3] = ffma2(xb.y, w1, acc[1][3]);
                }
                __syncthreads();
            }
            float* dst = g_part1[kh];
            #pragma unroll
            for (int jj = 0; jj < 2; jj++) {
                int j = j0 + tj * 2 + jj;
                *(ulonglong2*)&dst[(size_t)j * BB + tb * 8]     = make_ulonglong2(acc[jj][0], acc[jj][1]);
                *(ulonglong2*)&dst[(size_t)j * BB + tb * 8 + 4] = make_ulonglong2(acc[jj][2], acc[jj][3]);
            }
            __syncthreads();
            if (tid == 0) {
                st_rel(&g_pflags[cta * 32], (unsigned)(t + 1));
                while (ld_acq(&g_pflags[(cta ^ 1) * 32]) < (unsigned)(t + 1)) { }
            }
            __syncthreads();
            // fused LSTM1 cell for this CTA's 4 h values (all 128 batches)
            int* stok = (int*)(sh + 10240);
            if (tid < BB) stok[tid] = (t == 0) ? 0 : y[tid * TT + t];
            __syncthreads();
            const int hbase = jt * 8 + kh * 4;
            #pragma unroll
            for (int e = 0; e < 2; e++) {
                int idx = e * 256 + tid;
                int h = hbase + (idx >> 7), b = idx & 127;
                int tok = stok[b];
                int j4 = 4 * h;
                float gi = g_MembT[(size_t)j4 * 32 + tok]
                         + __ldcg(&g_part1[0][(size_t)j4 * BB + b])
                         + __ldcg(&g_part1[1][(size_t)j4 * BB + b]);
                float gf = g_MembT[(size_t)(j4 + 1) * 32 + tok]
                         + __ldcg(&g_part1[0][(size_t)(j4 + 1) * BB + b])
                         + __ldcg(&g_part1[1][(size_t)(j4 + 1) * BB + b]);
                float gg = g_MembT[(size_t)(j4 + 2) * 32 + tok]
                         + __ldcg(&g_part1[0][(size_t)(j4 + 2) * BB + b])
                         + __ldcg(&g_part1[1][(size_t)(j4 + 2) * BB + b]);
                float go = g_MembT[(size_t)(j4 + 3) * 32 + tok]
                         + __ldcg(&g_part1[0][(size_t)(j4 + 3) * BB + b])
                         + __ldcg(&g_part1[1][(size_t)(j4 + 3) * BB + b]);
                float c = sigf(gf) * g_c1T[h * BB + b] + sigf(gi) * tanhf(gg);
                g_c1T[h * BB + b] = c;
                g_xT[(WA + h) * BB + b] = sigf(go) * tanhf(c);
            }
        }
        gridbar(cta, tid, epoch);

        // ==== Stage B2: LSTM2 gates over x2=[h1;h2prev], K=640, 4-way k-split ====
        {
            float* xs = sh;          // [32][128]
            float* ws = sh + 4096;   // [32][16]
            const int jt = cta >> 2, ks = cta & 3;
            const int j0 = jt * 16, kb = ks * 160;
            const int tj = tid >> 5, tb = tid & 31;   // 2 j per tj, 4 b per tb
            u64 acc[2][2];
            acc[0][0] = acc[0][1] = acc[1][0] = acc[1][1] = 0ull;
            for (int kc = 0; kc < 160; kc += 32) {
                #pragma unroll
                for (int i = 0; i < 4; i++) {
                    int lin = i * 256 + tid;
                    int kk = lin >> 5, x4 = (lin & 31) * 4;
                    int kg = kb + kc + kk;
                    int row = (kg < 512) ? (WA + kg) : (640 + kg);   // 1152 + (kg-512)
                    *(float4*)&xs[kk * 128 + x4] = __ldcg((const float4*)&g_xT[row * BB + x4]);
                }
                {
                    int kk = tid >> 3, x2 = (tid & 7) * 2;
                    __half2 hv = *(const __half2*)(g_W2h + (size_t)(kb + kc + kk) * G2 + j0 + x2);
                    *(float2*)&ws[kk * 16 + x2] = __half22float2(hv);
                }
                __syncthreads();
                #pragma unroll
                for (int kk = 0; kk < 32; kk++) {
                    float2 wv = *(const float2*)&ws[kk * 16 + tj * 2];
                    u64 w0 = pack2(wv.x), w1 = pack2(wv.y);
                    ulonglong2 xa = *(const ulonglong2*)&xs[kk * 128 + tb * 4];
                    acc[0][0] = ffma2(xa.x, w0, acc[0][0]);
                    acc[0][1] = ffma2(xa.y, w0, acc[0][1]);
                    acc[1][0] = ffma2(xa.x, w1, acc[1][0]);
                    acc[1][1] = ffma2(xa.y, w1, acc[1][1]);
                }
                __syncthreads();
            }
            float* dst = g_part2[ks];
            #pragma unroll
            for (int jj = 0; jj < 2; jj++) {
                int j = j0 + tj * 2 + jj;
                *(ulonglong2*)&dst[(size_t)j * BB + tb * 4] = make_ulonglong2(acc[jj][0], acc[jj][1]);
            }
        }
        gridbar(cta, tid, epoch);

        // ==== Stage C: per-batch CTA: LSTM2 cell, q, attention, context, logits ====
        {
            const int b = cta;
            float* sg   = sh;            // 512 (gate-interleaved)
            float* h2s  = sh + 512;      // 128
            float* qs   = sh + 640;      // 128 (reused as ctx)
            float* satt = sh + 768;      // 400
            float* red  = sh + 1168;     // 8
            float* sinv = sh + 1176;     // 1
            float* cred = sh + 1184;     // 512

            #pragma unroll
            for (int e = 0; e < 2; e++) {
                int j = e * 256 + tid;
                float s = g_b2[j];
                #pragma unroll
                for (int ks = 0; ks < 4; ks++) s += __ldcg(&g_part2[ks][(size_t)j * BB + b]);
                sg[j] = s;
            }
            __syncthreads();
            if (tid < H2) {
                float4 g4 = *(const float4*)&sg[4 * tid];   // i,f,g,o
                float c = sigf(g4.y) * g_c2[b * H2 + tid] + sigf(g4.x) * tanhf(g4.z);
                g_c2[b * H2 + tid] = c;
                float hh = sigf(g4.w) * tanhf(c);
                g_xT[(1152 + tid) * BB + b] = hh;   // h2prev for next step
                h2s[tid] = hh;
            }
            __syncthreads();
            if (tid < PP) {
                const float4* wr = (const float4*)(Wq + tid * H2);
                const float4* h4 = (const float4*)h2s;
                float s = bq[tid];
                #pragma unroll 8
                for (int k4 = 0; k4 < 32; k4++) {
                    float4 w = wr[k4], h = h4[k4];
                    s += w.x*h.x + w.y*h.y + w.z*h.z + w.w*h.w;
                }
                qs[tid] = s;
            }
            __syncthreads();
            int lenb = lens[b];
            const float scale = 0.08838834764831845f;   // 1/sqrt(128)
            float pmax = -3.4e38f;
            for (int s = tid; s < SS; s += NTHR) {
                const uint4* kr = (const uint4*)(g_keysh + (size_t)(b * SS + s) * PP);
                const float4* q4 = (const float4*)qs;
                float d = 0.f;
                #pragma unroll
                for (int i = 0; i < 16; i++) {
                    uint4 u = kr[i];
                    const __half2* hp = (const __half2*)&u;
                    float2 f0 = __half22float2(hp[0]);
                    float2 f1 = __half22float2(hp[1]);
                    float2 f2 = __half22float2(hp[2]);
                    float2 f3 = __half22float2(hp[3]);
                    float4 qa = q4[2 * i], qb = q4[2 * i + 1];
                    d += f0.x*qa.x + f0.y*qa.y + f1.x*qa.z + f1.y*qa.w
                       + f2.x*qb.x + f2.y*qb.y + f3.x*qb.z + f3.y*qb.w;
                }
                d *= scale;
                if (s >= lenb) d = -1e9f;
                satt[s] = d;
                pmax = fmaxf(pmax, d);
            }
            float m = pmax;
            #pragma unroll
            for (int o = 16; o > 0; o >>= 1) m = fmaxf(m, __shfl_xor_sync(0xffffffffu, m, o));
            if ((tid & 31) == 0) red[tid >> 5] = m;
            __syncthreads();
            float mx = red[0];
            #pragma unroll
            for (int i = 1; i < 8; i++) mx = fmaxf(mx, red[i]);
            __syncthreads();
            float psum = 0.f;
            for (int s = tid; s < SS; s += NTHR) {
                float e = expf(satt[s] - mx);
                satt[s] = e;
                psum += e;
            }
            #pragma unroll
            for (int o = 16; o > 0; o >>= 1) psum += __shfl_xor_sync(0xffffffffu, psum, o);
            if ((tid & 31) == 0) red[tid >> 5] = psum;
            __syncthreads();
            if (tid == 0) {
                float s = 0.f;
                #pragma unroll
                for (int i = 0; i < 8; i++) s += red[i];
                sinv[0] = 1.f / s;
            }
            __syncthreads();
            float inv = sinv[0];
            {
                int p2 = tid & 63, sq = tid >> 6;    // 4 quarters of 100 s each
                const __half2* vp = (const __half2*)g_valsh + ((size_t)b * SS + sq * 100) * 64 + p2;
                float cx = 0.f, cy = 0.f;
                #pragma unroll 4
                for (int s = 0; s < 100; s++) {
                    float2 vf = __half22float2(vp[(size_t)s * 64]);
                    float a = satt[sq * 100 + s];
                    cx = fmaf(a, vf.x, cx);
                    cy = fmaf(a, vf.y, cy);
                }
                cred[sq * 128 + p2 * 2]     = cx;
                cred[sq * 128 + p2 * 2 + 1] = cy;
            }
            __syncthreads();
            if (tid < PP) {
                float c = (cred[tid] + cred[128 + tid] + cred[256 + tid] + cred[384 + tid]) * inv;
                g_xT[tid * BB + b] = c;   // ctx for next step
                qs[tid] = c;
            }
            __syncthreads();
            // logits: 240 threads (30 v x 8 chunks of 32), shuffle reduce per v
            {
                int v = tid >> 3, ch = tid & 7;
                float lg = 0.f;
                if (v < VV) {
                    const float* er = emb + v * EMBD + ch * 32;
                    const float* src = (ch < 4) ? (qs + ch * 32) : (h2s + (ch - 4) * 32);
                    #pragma unroll 8
                    for (int e = 0; e < 32; e++) lg += src[e] * er[e];
                }
                lg += __shfl_down_sync(0xffffffffu, lg, 4, 8);
                lg += __shfl_down_sync(0xffffffffu, lg, 2, 8);
                lg += __shfl_down_sync(0xffffffffu, lg, 1, 8);
                if (v < VV && ch == 0)
                    out[((size_t)b * VV + v) * TT + t] = lg + bout[v];   // predictions [B,V,T]
            }
            if (b == 0) {
                for (int s = tid; s < SS; s += NTHR)
                    out[PRED_N + t * SS + s] = satt[s] * inv;  // attention_plot [T,S]
            }
        }
        gridbar(cta, tid, epoch);
    }
}

// ---------------- launch ----------------
extern "C" void kernel_launch(void* const* d_in, const int* in_sizes, int n_in,
                              void* d_out, int out_size) {
    (void)in_sizes; (void)n_in; (void)out_size;
    const float* enc  = (const float*)d_in[0];
    const int*   lens = (const int*)d_in[1];
    const int*   y    = (const int*)d_in[2];
    const float* emb  = (const float*)d_in[3];
    const float* Wih1 = (const float*)d_in[4];
    const float* Whh1 = (const float*)d_in[5];
    const float* bih1 = (const float*)d_in[6];
    const float* bhh1 = (const float*)d_in[7];
    const float* Wih2 = (const float*)d_in[8];
    const float* Whh2 = (const float*)d_in[9];
    const float* bih2 = (const float*)d_in[10];
    const float* bhh2 = (const float*)d_in[11];
    const float* Wk   = (const float*)d_in[12];
    const float* bk   = (const float*)d_in[13];
    const float* Wv   = (const float*)d_in[14];
    const float* bv   = (const float*)d_in[15];
    const float* Wq   = (const float*)d_in[16];
    const float* bq   = (const float*)d_in[17];
    const float* bout = (const float*)d_in[18];
    float* out = (float*)d_out;

    int pack_n = 640 * G1 + 640 * G2 + G2;
    pack_kernel<<<(pack_n + 255) / 256, 256>>>(Wih1, Whh1, Wih2, Whh2, bih2, bhh2);
    memb_kernel<<<(VV * G1 + 255) / 256, 256>>>(emb, Wih1, bih1, bhh1);
    kv_kernel<<<dim3(400, 8), 256>>>(enc, Wk, bk, Wv, bv);
    init_kernel<<<640, 256>>>();
    loop_kernel<<<NCTA, NTHR>>>(y, lens, Wq, bq, emb, bout, out);
}